// round 12
// baseline (speedup 1.0000x reference)
#include <cuda_runtime.h>
#include <cuda_bf16.h>
#include <cstdint>

constexpr int Bsz = 512, Lz = 128, Hd = 1024, Od = 64, Sq = 256;
constexpr int G4 = 4096, IN0 = 192;
constexpr int K30  = 3 * (Od + Hd);   // 3264 logical
constexpr int K30P = 3328;            // padded to 26*128
constexpr int K31  = 3 * (2 * Hd);    // 6144 = 48*128
constexpr size_t BH = (size_t)Bsz * Hd;

constexpr int BK = 128;
constexpr int ROWB = 272;                       // 256B data + 16B pad
constexpr int TA = 64 * ROWB;                   // 17408
constexpr int TB = 64 * ROWB;                   // 17408
constexpr int STG = TA + TB;                    // 34816
constexpr int SMEM_TOTAL = 2 * STG;             // 69632 -> 3 CTAs/SM

// ---------------- device scratch ----------------
__device__ __align__(1024) __nv_bfloat16 g_W0[(size_t)G4 * K30P]; // [Wh | Wl | Wh | 0pad]
__device__ __align__(1024) __nv_bfloat16 g_W1[(size_t)G4 * K31];
__device__ __align__(1024) __nv_bfloat16 g_P0[2][(size_t)Bsz * K30P]; // [Ah | Ah | Al | 0pad]
__device__ __align__(1024) __nv_bfloat16 g_P1[2][(size_t)Bsz * K31];
__device__ float g_Wzp[(size_t)G4 * Lz];
__device__ float g_b0p[G4];
__device__ float g_b1p[G4];
__device__ float g_Gzp[(size_t)Bsz * G4];
__device__ float g_cT1[BH];     // c state transposed [k][b]
__device__ float g_cT2[BH];
__device__ float g_h2f[BH];

__device__ __forceinline__ float fsig(float x) { return 1.f / (1.f + __expf(-x)); }
__device__ __forceinline__ float ftanh(float x) {
    float e = __expf(2.f * x);
    return (e - 1.f) * (1.f / (e + 1.f));
}

__device__ __forceinline__ uint32_t s2u(const void* p) {
    uint32_t a;
    asm("{ .reg .u64 t; cvta.to.shared.u64 t, %1; cvt.u32.u64 %0, t; }" : "=r"(a) : "l"(p));
    return a;
}
__device__ __forceinline__ void cp16(uint32_t d, const void* s) {
    asm volatile("cp.async.cg.shared.global [%0], [%1], 16;" :: "r"(d), "l"(s) : "memory");
}
__device__ __forceinline__ void cp_commit() { asm volatile("cp.async.commit_group;" ::: "memory"); }
__device__ __forceinline__ void cp_wait1()  { asm volatile("cp.async.wait_group 1;" ::: "memory"); }
__device__ __forceinline__ void cp_wait0()  { asm volatile("cp.async.wait_group 0;" ::: "memory"); }

__device__ __forceinline__ void ldsm4(uint32_t* r, uint32_t addr) {
    asm volatile("ldmatrix.sync.aligned.m8n8.x4.shared.b16 {%0,%1,%2,%3}, [%4];"
                 : "=r"(r[0]), "=r"(r[1]), "=r"(r[2]), "=r"(r[3]) : "r"(addr));
}
__device__ __forceinline__ void mma16816(float* c, const uint32_t* a, const uint32_t* b) {
    asm volatile(
        "mma.sync.aligned.m16n8k16.row.col.f32.bf16.bf16.f32 "
        "{%0,%1,%2,%3}, {%4,%5,%6,%7}, {%8,%9}, {%0,%1,%2,%3};"
        : "+f"(c[0]), "+f"(c[1]), "+f"(c[2]), "+f"(c[3])
        : "r"(a[0]), "r"(a[1]), "r"(a[2]), "r"(a[3]), "r"(b[0]), "r"(b[1]));
}

// ---------------- prepass: permute(g*H+k -> 4k+g) + bf16 hi/lo split + K-concat ----------------
__global__ void pack_weights(const float* __restrict__ Wih0, const float* __restrict__ Whh0,
                             const float* __restrict__ bih0, const float* __restrict__ bhh0,
                             const float* __restrict__ Wih1, const float* __restrict__ Whh1,
                             const float* __restrict__ bih1, const float* __restrict__ bhh1)
{
    int n = blockIdx.x, k = n >> 2, g = n & 3, src = g * Hd + k;
    __nv_bfloat16* w0 = g_W0 + (size_t)n * K30P;
    __nv_bfloat16* w1 = g_W1 + (size_t)n * K31;
    for (int j = threadIdx.x; j < Od + Hd; j += 256) {
        float w = (j < Od) ? Wih0[(size_t)src * IN0 + Lz + j] : Whh0[(size_t)src * Hd + (j - Od)];
        __nv_bfloat16 h = __float2bfloat16(w);
        __nv_bfloat16 l = __float2bfloat16(w - __bfloat162float(h));
        w0[j] = h; w0[1088 + j] = l; w0[2176 + j] = h;
    }
    for (int j = K30 + threadIdx.x; j < K30P; j += 256)
        w0[j] = __float2bfloat16(0.f);
    for (int j = threadIdx.x; j < 2 * Hd; j += 256) {
        float w = (j < Hd) ? Wih1[(size_t)src * Hd + j] : Whh1[(size_t)src * Hd + (j - Hd)];
        __nv_bfloat16 h = __float2bfloat16(w);
        __nv_bfloat16 l = __float2bfloat16(w - __bfloat162float(h));
        w1[j] = h; w1[2048 + j] = l; w1[4096 + j] = h;
    }
    for (int j = threadIdx.x; j < Lz; j += 256)
        g_Wzp[(size_t)n * Lz + j] = Wih0[(size_t)src * IN0 + j];
    if (threadIdx.x == 0) {
        g_b0p[n] = bih0[src] + bhh0[src];
        g_b1p[n] = bih1[src] + bhh1[src];
    }
}

// ---------------- init: h0/c0 projections -> panels / cT; zero fb + pad slots ----------------
__global__ void init_hc(const float* __restrict__ z,
                        const float* __restrict__ Wh, const float* __restrict__ bh,
                        const float* __restrict__ Wc, const float* __restrict__ bc)
{
    __shared__ float zs[8 * Lz];
    int b0 = blockIdx.y * 8;
    for (int i = threadIdx.x; i < 8 * Lz / 4; i += 128)
        ((float4*)zs)[i] = ((const float4*)(z + (size_t)b0 * Lz))[i];
    __syncthreads();
    int k = blockIdx.x * 128 + threadIdx.x;
    const float4* wh = (const float4*)(Wh + (size_t)k * Lz);
    const float4* wc = (const float4*)(Wc + (size_t)k * Lz);
    float ah[8] = {0}, ac[8] = {0};
#pragma unroll 8
    for (int l = 0; l < Lz / 4; ++l) {
        float4 wv = wh[l], cv = wc[l];
#pragma unroll
        for (int r = 0; r < 8; ++r) {
            float4 zv = ((float4*)zs)[r * (Lz / 4) + l];
            ah[r] += zv.x * wv.x + zv.y * wv.y + zv.z * wv.z + zv.w * wv.w;
            ac[r] += zv.x * cv.x + zv.y * cv.y + zv.z * cv.z + zv.w * cv.w;
        }
    }
    float bhv = bh[k], bcv = bc[k];
#pragma unroll
    for (int r = 0; r < 8; ++r) {
        int b = b0 + r;
        float hv = ah[r] + bhv, cv = ac[r] + bcv;
        g_cT1[(size_t)k * Bsz + b] = cv;
        g_cT2[(size_t)k * Bsz + b] = cv;
        __nv_bfloat16 hh = __float2bfloat16(hv);
        __nv_bfloat16 hl = __float2bfloat16(hv - __bfloat162float(hh));
        __nv_bfloat16* p0 = g_P0[0] + (size_t)b * K30P;
        p0[64 + k] = hh; p0[1152 + k] = hh; p0[2240 + k] = hl;
        __nv_bfloat16* p1 = g_P1[0] + (size_t)b * K31;
        p1[1024 + k] = hh; p1[3072 + k] = hh; p1[5120 + k] = hl;
    }
    if (blockIdx.x == 0 && threadIdx.x < 64) {
        int o = threadIdx.x;
        __nv_bfloat16 zz = __float2bfloat16(0.f);
#pragma unroll
        for (int r = 0; r < 8; ++r) {
            int b = b0 + r;
            __nv_bfloat16* pa = g_P0[0] + (size_t)b * K30P;
            __nv_bfloat16* pb = g_P0[1] + (size_t)b * K30P;
            pa[o] = zz; pa[1088 + o] = zz; pa[2176 + o] = zz;
            pa[K30 + o] = zz; pb[K30 + o] = zz;      // K-pad, both buffers
        }
    }
}

// ---------------- Gzp = z @ Wzp.T + b0p (fp32, exact, step-invariant) ----------------
__global__ void gz_gemm(const float* __restrict__ z)
{
    __shared__ float zs[8 * Lz];
    int b0 = blockIdx.y * 8;
    for (int i = threadIdx.x; i < 8 * Lz / 4; i += 128)
        ((float4*)zs)[i] = ((const float4*)(z + (size_t)b0 * Lz))[i];
    __syncthreads();
    int n = blockIdx.x * 128 + threadIdx.x;
    const float4* w = (const float4*)(g_Wzp + (size_t)n * Lz);
    float acc[8] = {0};
#pragma unroll 8
    for (int l = 0; l < Lz / 4; ++l) {
        float4 wv = w[l];
#pragma unroll
        for (int r = 0; r < 8; ++r) {
            float4 zv = ((float4*)zs)[r * (Lz / 4) + l];
            acc[r] += zv.x * wv.x + zv.y * wv.y + zv.z * wv.z + zv.w * wv.w;
        }
    }
    float bb = g_b0p[n];
#pragma unroll
    for (int r = 0; r < 8; ++r)
        g_Gzp[(size_t)(b0 + r) * G4 + n] = acc[r] + bb;
}

// ---------------- HMMA GEMM (64x64 tiles, 512 CTAs, BK=128) + fused LSTM epilogue ----------------
struct EpiDst { __nv_bfloat16 *hi0, *hi1, *lo; int stride; };

__global__ __launch_bounds__(128) void lstm_mma(
    const __nv_bfloat16* __restrict__ act, int K3, int nch,
    const __nv_bfloat16* __restrict__ W,
    const float* __restrict__ initT, const float* __restrict__ bias,
    float* __restrict__ cT,
    EpiDst e0, EpiDst e1, float* __restrict__ h32)
{
    extern __shared__ char smem[];
    uint32_t sbase = s2u(smem);
    int tid = threadIdx.x;
    int n0 = blockIdx.x * 64, m0 = blockIdx.y * 64;
    int warp = tid >> 5, lane = tid & 31;
    int wm = warp >> 1, wn = warp & 1;      // 2 x 2 warp grid, warp tile 32 x 32
    int gid = lane >> 2, tid2 = lane & 3;

    float acc[2][4][4];
#pragma unroll
    for (int mi = 0; mi < 2; ++mi)
#pragma unroll
        for (int nj = 0; nj < 4; ++nj)
#pragma unroll
            for (int q = 0; q < 4; ++q) acc[mi][nj][q] = 0.f;

    const __nv_bfloat16* ag = act + (size_t)m0 * K3;
    const __nv_bfloat16* wg = W + (size_t)n0 * K3;

    // ldmatrix per-lane base offsets (bytes within tile) — validated mapping
    uint32_t aOff = (uint32_t)(wm * 32 + (lane & 15)) * ROWB + ((lane >> 4) * 16);
    uint32_t bOff = (uint32_t)(wn * 32 + (lane & 7) + ((lane >> 4) * 8)) * ROWB
                  + (((lane >> 3) & 1) * 16);

#define LOAD_CHUNK(CH, BUF) {                                                     \
        uint32_t sa = sbase + (BUF) * STG;                                        \
        uint32_t sb2 = sa + TA;                                                   \
        const __nv_bfloat16* ap = ag + (CH) * BK;                                 \
        const __nv_bfloat16* wp = wg + (CH) * BK;                                 \
        _Pragma("unroll")                                                         \
        for (int j = 0; j < 8; ++j) {                                             \
            int i = tid + 128 * j;                                                \
            int row = i >> 4, grp = i & 15;                                       \
            cp16(sa + row * ROWB + grp * 16, ap + (size_t)row * K3 + grp * 8);    \
        }                                                                         \
        _Pragma("unroll")                                                         \
        for (int j = 0; j < 8; ++j) {                                             \
            int i = tid + 128 * j;                                                \
            int row = i >> 4, grp = i & 15;                                       \
            cp16(sb2 + row * ROWB + grp * 16, wp + (size_t)row * K3 + grp * 8);   \
        }                                                                         \
        cp_commit();                                                              \
    }

    LOAD_CHUNK(0, 0)
    for (int ch = 0; ch < nch; ++ch) {
        int buf = ch & 1;
        if (ch + 1 < nch) { LOAD_CHUNK(ch + 1, buf ^ 1) cp_wait1(); }
        else cp_wait0();
        __syncthreads();

        uint32_t aB = sbase + buf * STG + aOff;
        uint32_t bB = sbase + buf * STG + TA + bOff;
#pragma unroll
        for (int ks = 0; ks < 8; ++ks) {
            uint32_t Af[2][4], Bf[2][4];
#pragma unroll
            for (int mi = 0; mi < 2; ++mi) ldsm4(Af[mi], aB + mi * 16 * ROWB + ks * 32);
#pragma unroll
            for (int p = 0; p < 2; ++p)    ldsm4(Bf[p], bB + p * 16 * ROWB + ks * 32);
#pragma unroll
            for (int mi = 0; mi < 2; ++mi)
#pragma unroll
                for (int p = 0; p < 2; ++p) {
                    mma16816(acc[mi][2 * p],     Af[mi], &Bf[p][0]);
                    mma16816(acc[mi][2 * p + 1], Af[mi], &Bf[p][2]);
                }
        }
        __syncthreads();
    }
#undef LOAD_CHUNK

    // ---- epilogue: 2 passes of 64 rows x 32 gate cols through SMEM ----
    float* gbuf = (float*)smem;
    const int GP = 36;
    for (int nq = 0; nq < 2; ++nq) {
        if (wn == nq) {
#pragma unroll
            for (int mi = 0; mi < 2; ++mi)
#pragma unroll
                for (int nj = 0; nj < 4; ++nj) {
                    int r = wm * 32 + mi * 16 + gid;
                    int cl = nj * 8 + tid2 * 2;
                    gbuf[r * GP + cl]           = acc[mi][nj][0];
                    gbuf[r * GP + cl + 1]       = acc[mi][nj][1];
                    gbuf[(r + 8) * GP + cl]     = acc[mi][nj][2];
                    gbuf[(r + 8) * GP + cl + 1] = acc[mi][nj][3];
                }
        }
        __syncthreads();
#pragma unroll
        for (int idx = tid; idx < 512; idx += 128) {
            int b = idx >> 3, g = idx & 7;
            int bg = m0 + b;
            float4 a4 = *(const float4*)&gbuf[b * GP + g * 4];
            float4 bb = initT
                ? *(const float4*)(initT + (size_t)bg * G4 + n0 + nq * 32 + g * 4)
                : *(const float4*)(bias + n0 + nq * 32 + g * 4);
            float i_ = fsig(a4.x + bb.x);
            float f_ = fsig(a4.y + bb.y);
            float g_ = ftanh(a4.z + bb.z);
            float o_ = fsig(a4.w + bb.w);
            int k = (n0 >> 2) + nq * 8 + g;
            float c = cT[(size_t)k * Bsz + bg];
            float cn = f_ * c + i_ * g_;
            cT[(size_t)k * Bsz + bg] = cn;
            float h = o_ * ftanh(cn);
            __nv_bfloat16 hh = __float2bfloat16(h);
            __nv_bfloat16 hl = __float2bfloat16(h - __bfloat162float(hh));
            e0.hi0[(size_t)bg * e0.stride + k] = hh;
            e0.hi1[(size_t)bg * e0.stride + k] = hh;
            e0.lo [(size_t)bg * e0.stride + k] = hl;
            if (e1.hi0) {
                e1.hi0[(size_t)bg * e1.stride + k] = hh;
                e1.hi1[(size_t)bg * e1.stride + k] = hh;
                e1.lo [(size_t)bg * e1.stride + k] = hl;
            }
            if (h32) h32[(size_t)bg * Hd + k] = h;
        }
        __syncthreads();
    }
}

// ---------------- out = h2 @ Wout.T + bout -> d_out[:,t,:] + bf16 feedback ----------------
__global__ void out_proj(const float* __restrict__ h2, const float* __restrict__ Wout,
                         const float* __restrict__ bout, float* __restrict__ dout, int t,
                         __nv_bfloat16* __restrict__ P0next)
{
    __shared__ float hs[Hd];
    int b = blockIdx.x, o = threadIdx.x;
    for (int i = o; i < Hd / 4; i += 64)
        ((float4*)hs)[i] = ((const float4*)(h2 + (size_t)b * Hd))[i];
    __syncthreads();
    const float4* w = (const float4*)(Wout + (size_t)o * Hd);
    float acc = 0.f;
#pragma unroll 8
    for (int i = 0; i < Hd / 4; ++i) {
        float4 wv = w[i], hv = ((float4*)hs)[i];
        acc += wv.x * hv.x + wv.y * hv.y + wv.z * hv.z + wv.w * hv.w;
    }
    acc += bout[o];
    __nv_bfloat16 hh = __float2bfloat16(acc);
    __nv_bfloat16 hl = __float2bfloat16(acc - __bfloat162float(hh));
    __nv_bfloat16* p = P0next + (size_t)b * K30P;
    p[o] = hh; p[1088 + o] = hh; p[2176 + o] = hl;
    dout[(size_t)b * Sq * Od + (size_t)t * Od + o] = acc;
}

// ---------------- host ----------------
extern "C" void kernel_launch(void* const* d_in, const int* in_sizes, int n_in,
                              void* d_out, int out_size)
{
    const float* z    = (const float*)d_in[0];
    const float* Wh   = (const float*)d_in[1];
    const float* bh   = (const float*)d_in[2];
    const float* Wc   = (const float*)d_in[3];
    const float* bc   = (const float*)d_in[4];
    const float* Wih0 = (const float*)d_in[5];
    const float* Whh0 = (const float*)d_in[6];
    const float* bih0 = (const float*)d_in[7];
    const float* bhh0 = (const float*)d_in[8];
    const float* Wih1 = (const float*)d_in[9];
    const float* Whh1 = (const float*)d_in[10];
    const float* bih1 = (const float*)d_in[11];
    const float* bhh1 = (const float*)d_in[12];
    const float* Wout = (const float*)d_in[13];
    const float* bout = (const float*)d_in[14];
    float* out = (float*)d_out;

    __nv_bfloat16 *p_W0, *p_W1, *p_P0, *p_P1;
    float *p_Gzp, *p_b1p, *p_cT1, *p_cT2, *p_h2f;
    cudaGetSymbolAddress((void**)&p_W0,  g_W0);
    cudaGetSymbolAddress((void**)&p_W1,  g_W1);
    cudaGetSymbolAddress((void**)&p_P0,  g_P0);
    cudaGetSymbolAddress((void**)&p_P1,  g_P1);
    cudaGetSymbolAddress((void**)&p_Gzp, g_Gzp);
    cudaGetSymbolAddress((void**)&p_b1p, g_b1p);
    cudaGetSymbolAddress((void**)&p_cT1, g_cT1);
    cudaGetSymbolAddress((void**)&p_cT2, g_cT2);
    cudaGetSymbolAddress((void**)&p_h2f, g_h2f);

    cudaFuncSetAttribute(lstm_mma, cudaFuncAttributeMaxDynamicSharedMemorySize, SMEM_TOTAL);

    pack_weights<<<G4, 256>>>(Wih0, Whh0, bih0, bhh0, Wih1, Whh1, bih1, bhh1);
    init_hc<<<dim3(Hd / 128, Bsz / 8), 128>>>(z, Wh, bh, Wc, bc);
    gz_gemm<<<dim3(G4 / 128, Bsz / 8), 128>>>(z);

    dim3 gg(G4 / 64, Bsz / 64);     // 64 x 8 = 512 CTAs
    const size_t P0sz = (size_t)Bsz * K30P, P1sz = (size_t)Bsz * K31;
    for (int t = 0; t < Sq; ++t) {
        int cur = t & 1, nxt = cur ^ 1;
        __nv_bfloat16* P0c = p_P0 + cur * P0sz;
        __nv_bfloat16* P0n = p_P0 + nxt * P0sz;
        __nv_bfloat16* P1c = p_P1 + cur * P1sz;
        __nv_bfloat16* P1n = p_P1 + nxt * P1sz;

        // layer 0: gates = Gzp + [fbh h1h | fbh h1h | fbl h1l | 0] @ W0cat.T
        EpiDst e0{P1c + 0,  P1c + 2048, P1c + 4096, K31};   // h1n -> layer1 panel (this step)
        EpiDst e1{P0n + 64, P0n + 1152, P0n + 2240, K30P};  // h1n -> layer0 panel (next step)
        lstm_mma<<<gg, 128, SMEM_TOTAL>>>(P0c, K30P, K30P / BK, p_W0,
                                          p_Gzp, nullptr, p_cT1, e0, e1, nullptr);

        // layer 1: gates = b1p + [h1nh h2h | h1nh h2h | h1nl h2l] @ W1cat.T
        EpiDst f0{P1n + 1024, P1n + 3072, P1n + 5120, K31}; // h2 -> layer1 panel (next step)
        EpiDst f1{nullptr, nullptr, nullptr, 0};
        lstm_mma<<<gg, 128, SMEM_TOTAL>>>(P1c, K31, K31 / BK, p_W1,
                                          nullptr, p_b1p, p_cT2, f0, f1, p_h2f);

        out_proj<<<Bsz, 64>>>(p_h2f, Wout, bout, out, t, P0n);
    }
}

// round 13
// speedup vs baseline: 1.1106x; 1.1106x over previous
#include <cuda_runtime.h>
#include <cuda_bf16.h>
#include <cstdint>

constexpr int Bsz = 512, Lz = 128, Hd = 1024, Od = 64, Sq = 256;
constexpr int G4 = 4096, IN0 = 192;
constexpr int K30  = 3 * (Od + Hd);   // 3264 logical
constexpr int K30P = 3328;            // padded to 26*128
constexpr int K31  = 3 * (2 * Hd);    // 6144 = 48*128
constexpr size_t BH = (size_t)Bsz * Hd;

constexpr int BK = 128;
constexpr int ROWB = 272;                       // 256B data + 16B pad
constexpr int TA = 128 * ROWB;                  // 34816
constexpr int TB = 64 * ROWB;                   // 17408
constexpr int STG = TA + TB;                    // 52224
constexpr int SMEM_TOTAL = 2 * STG;             // 104448 -> 2 CTAs/SM

// ---------------- device scratch ----------------
__device__ __align__(1024) __nv_bfloat16 g_W0[(size_t)G4 * K30P]; // [Wh | Wl | Wh | 0pad]
__device__ __align__(1024) __nv_bfloat16 g_W1[(size_t)G4 * K31];
__device__ __align__(1024) __nv_bfloat16 g_P0[2][(size_t)Bsz * K30P]; // [Ah | Ah | Al | 0pad]
__device__ __align__(1024) __nv_bfloat16 g_P1[2][(size_t)Bsz * K31];
__device__ float g_Wzp[(size_t)G4 * Lz];
__device__ float g_b0p[G4];
__device__ float g_b1p[G4];
__device__ float g_Gzp[(size_t)Bsz * G4];
__device__ float g_cT1[BH];     // c state transposed [k][b]
__device__ float g_cT2[BH];
__device__ float g_h2f[BH];

__device__ __forceinline__ float fsig(float x) { return 1.f / (1.f + __expf(-x)); }
__device__ __forceinline__ float ftanh(float x) {
    float e = __expf(2.f * x);
    return (e - 1.f) * (1.f / (e + 1.f));
}

__device__ __forceinline__ uint32_t s2u(const void* p) {
    uint32_t a;
    asm("{ .reg .u64 t; cvta.to.shared.u64 t, %1; cvt.u32.u64 %0, t; }" : "=r"(a) : "l"(p));
    return a;
}
__device__ __forceinline__ void cp16(uint32_t d, const void* s) {
    asm volatile("cp.async.cg.shared.global [%0], [%1], 16;" :: "r"(d), "l"(s) : "memory");
}
__device__ __forceinline__ void cp_commit() { asm volatile("cp.async.commit_group;" ::: "memory"); }
__device__ __forceinline__ void cp_wait0()  { asm volatile("cp.async.wait_group 0;" ::: "memory"); }

__device__ __forceinline__ void ldsm4(uint32_t* r, uint32_t addr) {
    asm volatile("ldmatrix.sync.aligned.m8n8.x4.shared.b16 {%0,%1,%2,%3}, [%4];"
                 : "=r"(r[0]), "=r"(r[1]), "=r"(r[2]), "=r"(r[3]) : "r"(addr));
}
__device__ __forceinline__ void mma16816(float* c, const uint32_t* a, const uint32_t* b) {
    asm volatile(
        "mma.sync.aligned.m16n8k16.row.col.f32.bf16.bf16.f32 "
        "{%0,%1,%2,%3}, {%4,%5,%6,%7}, {%8,%9}, {%0,%1,%2,%3};"
        : "+f"(c[0]), "+f"(c[1]), "+f"(c[2]), "+f"(c[3])
        : "r"(a[0]), "r"(a[1]), "r"(a[2]), "r"(a[3]), "r"(b[0]), "r"(b[1]));
}

// ---------------- prepass: permute(g*H+k -> 4k+g) + bf16 hi/lo split + K-concat ----------------
__global__ void pack_weights(const float* __restrict__ Wih0, const float* __restrict__ Whh0,
                             const float* __restrict__ bih0, const float* __restrict__ bhh0,
                             const float* __restrict__ Wih1, const float* __restrict__ Whh1,
                             const float* __restrict__ bih1, const float* __restrict__ bhh1)
{
    int n = blockIdx.x, k = n >> 2, g = n & 3, src = g * Hd + k;
    __nv_bfloat16* w0 = g_W0 + (size_t)n * K30P;
    __nv_bfloat16* w1 = g_W1 + (size_t)n * K31;
    for (int j = threadIdx.x; j < Od + Hd; j += 256) {
        float w = (j < Od) ? Wih0[(size_t)src * IN0 + Lz + j] : Whh0[(size_t)src * Hd + (j - Od)];
        __nv_bfloat16 h = __float2bfloat16(w);
        __nv_bfloat16 l = __float2bfloat16(w - __bfloat162float(h));
        w0[j] = h; w0[1088 + j] = l; w0[2176 + j] = h;
    }
    for (int j = K30 + threadIdx.x; j < K30P; j += 256)
        w0[j] = __float2bfloat16(0.f);
    for (int j = threadIdx.x; j < 2 * Hd; j += 256) {
        float w = (j < Hd) ? Wih1[(size_t)src * Hd + j] : Whh1[(size_t)src * Hd + (j - Hd)];
        __nv_bfloat16 h = __float2bfloat16(w);
        __nv_bfloat16 l = __float2bfloat16(w - __bfloat162float(h));
        w1[j] = h; w1[2048 + j] = l; w1[4096 + j] = h;
    }
    for (int j = threadIdx.x; j < Lz; j += 256)
        g_Wzp[(size_t)n * Lz + j] = Wih0[(size_t)src * IN0 + j];
    if (threadIdx.x == 0) {
        g_b0p[n] = bih0[src] + bhh0[src];
        g_b1p[n] = bih1[src] + bhh1[src];
    }
}

// ---------------- init: h0/c0 projections -> panels / cT; zero fb + pad slots ----------------
__global__ void init_hc(const float* __restrict__ z,
                        const float* __restrict__ Wh, const float* __restrict__ bh,
                        const float* __restrict__ Wc, const float* __restrict__ bc)
{
    __shared__ float zs[8 * Lz];
    int b0 = blockIdx.y * 8;
    for (int i = threadIdx.x; i < 8 * Lz / 4; i += 128)
        ((float4*)zs)[i] = ((const float4*)(z + (size_t)b0 * Lz))[i];
    __syncthreads();
    int k = blockIdx.x * 128 + threadIdx.x;
    const float4* wh = (const float4*)(Wh + (size_t)k * Lz);
    const float4* wc = (const float4*)(Wc + (size_t)k * Lz);
    float ah[8] = {0}, ac[8] = {0};
#pragma unroll 8
    for (int l = 0; l < Lz / 4; ++l) {
        float4 wv = wh[l], cv = wc[l];
#pragma unroll
        for (int r = 0; r < 8; ++r) {
            float4 zv = ((float4*)zs)[r * (Lz / 4) + l];
            ah[r] += zv.x * wv.x + zv.y * wv.y + zv.z * wv.z + zv.w * wv.w;
            ac[r] += zv.x * cv.x + zv.y * cv.y + zv.z * cv.z + zv.w * cv.w;
        }
    }
    float bhv = bh[k], bcv = bc[k];
#pragma unroll
    for (int r = 0; r < 8; ++r) {
        int b = b0 + r;
        float hv = ah[r] + bhv, cv = ac[r] + bcv;
        g_cT1[(size_t)k * Bsz + b] = cv;
        g_cT2[(size_t)k * Bsz + b] = cv;
        __nv_bfloat16 hh = __float2bfloat16(hv);
        __nv_bfloat16 hl = __float2bfloat16(hv - __bfloat162float(hh));
        __nv_bfloat16* p0 = g_P0[0] + (size_t)b * K30P;
        p0[64 + k] = hh; p0[1152 + k] = hh; p0[2240 + k] = hl;
        __nv_bfloat16* p1 = g_P1[0] + (size_t)b * K31;
        p1[1024 + k] = hh; p1[3072 + k] = hh; p1[5120 + k] = hl;
    }
    if (blockIdx.x == 0 && threadIdx.x < 64) {
        int o = threadIdx.x;
        __nv_bfloat16 zz = __float2bfloat16(0.f);
#pragma unroll
        for (int r = 0; r < 8; ++r) {
            int b = b0 + r;
            __nv_bfloat16* pa = g_P0[0] + (size_t)b * K30P;
            __nv_bfloat16* pb = g_P0[1] + (size_t)b * K30P;
            pa[o] = zz; pa[1088 + o] = zz; pa[2176 + o] = zz;
            pa[K30 + o] = zz; pb[K30 + o] = zz;      // K-pad, both buffers
        }
    }
}

// ---------------- Gzp = z @ Wzp.T + b0p (fp32, exact, step-invariant) ----------------
__global__ void gz_gemm(const float* __restrict__ z)
{
    __shared__ float zs[8 * Lz];
    int b0 = blockIdx.y * 8;
    for (int i = threadIdx.x; i < 8 * Lz / 4; i += 128)
        ((float4*)zs)[i] = ((const float4*)(z + (size_t)b0 * Lz))[i];
    __syncthreads();
    int n = blockIdx.x * 128 + threadIdx.x;
    const float4* w = (const float4*)(g_Wzp + (size_t)n * Lz);
    float acc[8] = {0};
#pragma unroll 8
    for (int l = 0; l < Lz / 4; ++l) {
        float4 wv = w[l];
#pragma unroll
        for (int r = 0; r < 8; ++r) {
            float4 zv = ((float4*)zs)[r * (Lz / 4) + l];
            acc[r] += zv.x * wv.x + zv.y * wv.y + zv.z * wv.z + zv.w * wv.w;
        }
    }
    float bb = g_b0p[n];
#pragma unroll
    for (int r = 0; r < 8; ++r)
        g_Gzp[(size_t)(b0 + r) * G4 + n] = acc[r] + bb;
}

// ---------------- HMMA GEMM (128x64, BK=128, 1 bar/chunk) + fused LSTM epilogue ----------------
struct EpiDst { __nv_bfloat16 *hi0, *hi1, *lo; int stride; };

__global__ __launch_bounds__(256) void lstm_mma(
    const __nv_bfloat16* __restrict__ act, int K3, int nch,
    const __nv_bfloat16* __restrict__ W,
    const float* __restrict__ initT, const float* __restrict__ bias,
    float* __restrict__ cT,
    EpiDst e0, EpiDst e1, float* __restrict__ h32)
{
    extern __shared__ char smem[];
    uint32_t sbase = s2u(smem);
    int tid = threadIdx.x;
    int n0 = blockIdx.x * 64, m0 = blockIdx.y * 128;
    int warp = tid >> 5, lane = tid & 31;
    int wm = warp >> 1, wn = warp & 1;      // 4 x 2 warp grid, warp tile 32 x 32
    int gid = lane >> 2, tid2 = lane & 3;

    float acc[2][4][4];
#pragma unroll
    for (int mi = 0; mi < 2; ++mi)
#pragma unroll
        for (int nj = 0; nj < 4; ++nj)
#pragma unroll
            for (int q = 0; q < 4; ++q) acc[mi][nj][q] = 0.f;

    const __nv_bfloat16* ag = act + (size_t)m0 * K3;
    const __nv_bfloat16* wg = W + (size_t)n0 * K3;

    // ldmatrix per-lane base offsets (bytes within tile) — validated mapping
    uint32_t aOff = (uint32_t)(wm * 32 + (lane & 15)) * ROWB + ((lane >> 4) * 16);
    uint32_t bOff = (uint32_t)(wn * 32 + (lane & 7) + ((lane >> 4) * 8)) * ROWB
                  + (((lane >> 3) & 1) * 16);

#define LOAD_CHUNK(CH, BUF) {                                                     \
        uint32_t sa = sbase + (BUF) * STG;                                        \
        uint32_t sb2 = sa + TA;                                                   \
        const __nv_bfloat16* ap = ag + (CH) * BK;                                 \
        const __nv_bfloat16* wp = wg + (CH) * BK;                                 \
        _Pragma("unroll")                                                         \
        for (int j = 0; j < 8; ++j) {                                             \
            int i = tid + 256 * j;                                                \
            int row = i >> 4, grp = i & 15;                                       \
            cp16(sa + row * ROWB + grp * 16, ap + (size_t)row * K3 + grp * 8);    \
        }                                                                         \
        _Pragma("unroll")                                                         \
        for (int j = 0; j < 4; ++j) {                                             \
            int i = tid + 256 * j;                                                \
            int row = i >> 4, grp = i & 15;                                       \
            cp16(sb2 + row * ROWB + grp * 16, wp + (size_t)row * K3 + grp * 8);   \
        }                                                                         \
        cp_commit();                                                              \
    }

    LOAD_CHUNK(0, 0)
    for (int ch = 0; ch < nch; ++ch) {
        int buf = ch & 1;
        // wait for this chunk's data, then ONE barrier. After the barrier it is
        // safe to overwrite buf^1: every warp's chunk ch-1 compute (which read
        // buf^1) precedes this barrier in its program order.
        cp_wait0();
        __syncthreads();
        if (ch + 1 < nch) LOAD_CHUNK(ch + 1, buf ^ 1)

        uint32_t aB = sbase + buf * STG + aOff;
        uint32_t bB = sbase + buf * STG + TA + bOff;
#pragma unroll
        for (int ks = 0; ks < 8; ++ks) {
            uint32_t Af[2][4], Bf[2][4];
#pragma unroll
            for (int mi = 0; mi < 2; ++mi) ldsm4(Af[mi], aB + mi * 16 * ROWB + ks * 32);
#pragma unroll
            for (int p = 0; p < 2; ++p)    ldsm4(Bf[p], bB + p * 16 * ROWB + ks * 32);
#pragma unroll
            for (int mi = 0; mi < 2; ++mi)
#pragma unroll
                for (int p = 0; p < 2; ++p) {
                    mma16816(acc[mi][2 * p],     Af[mi], &Bf[p][0]);
                    mma16816(acc[mi][2 * p + 1], Af[mi], &Bf[p][2]);
                }
        }
    }
#undef LOAD_CHUNK
    __syncthreads();   // all ldsm done before smem reuse below

    // ---- epilogue: 2 passes of 128 rows x 32 gate cols through SMEM ----
    float* gbuf = (float*)smem;
    const int GP = 36;
    for (int nq = 0; nq < 2; ++nq) {
        if (wn == nq) {
#pragma unroll
            for (int mi = 0; mi < 2; ++mi)
#pragma unroll
                for (int nj = 0; nj < 4; ++nj) {
                    int r = wm * 32 + mi * 16 + gid;
                    int cl = nj * 8 + tid2 * 2;
                    gbuf[r * GP + cl]           = acc[mi][nj][0];
                    gbuf[r * GP + cl + 1]       = acc[mi][nj][1];
                    gbuf[(r + 8) * GP + cl]     = acc[mi][nj][2];
                    gbuf[(r + 8) * GP + cl + 1] = acc[mi][nj][3];
                }
        }
        __syncthreads();
#pragma unroll
        for (int idx = tid; idx < 1024; idx += 256) {
            int b = idx >> 3, g = idx & 7;
            int bg = m0 + b;
            float4 a4 = *(const float4*)&gbuf[b * GP + g * 4];
            float4 bb = initT
                ? *(const float4*)(initT + (size_t)bg * G4 + n0 + nq * 32 + g * 4)
                : *(const float4*)(bias + n0 + nq * 32 + g * 4);
            float i_ = fsig(a4.x + bb.x);
            float f_ = fsig(a4.y + bb.y);
            float g_ = ftanh(a4.z + bb.z);
            float o_ = fsig(a4.w + bb.w);
            int k = (n0 >> 2) + nq * 8 + g;
            float c = cT[(size_t)k * Bsz + bg];
            float cn = f_ * c + i_ * g_;
            cT[(size_t)k * Bsz + bg] = cn;
            float h = o_ * ftanh(cn);
            __nv_bfloat16 hh = __float2bfloat16(h);
            __nv_bfloat16 hl = __float2bfloat16(h - __bfloat162float(hh));
            e0.hi0[(size_t)bg * e0.stride + k] = hh;
            e0.hi1[(size_t)bg * e0.stride + k] = hh;
            e0.lo [(size_t)bg * e0.stride + k] = hl;
            if (e1.hi0) {
                e1.hi0[(size_t)bg * e1.stride + k] = hh;
                e1.hi1[(size_t)bg * e1.stride + k] = hh;
                e1.lo [(size_t)bg * e1.stride + k] = hl;
            }
            if (h32) h32[(size_t)bg * Hd + k] = h;
        }
        __syncthreads();
    }
}

// ---------------- out = h2 @ Wout.T + bout -> d_out[:,t,:] + bf16 feedback ----------------
__global__ void out_proj(const float* __restrict__ h2, const float* __restrict__ Wout,
                         const float* __restrict__ bout, float* __restrict__ dout, int t,
                         __nv_bfloat16* __restrict__ P0next)
{
    __shared__ float hs[Hd];
    int b = blockIdx.x, o = threadIdx.x;
    for (int i = o; i < Hd / 4; i += 64)
        ((float4*)hs)[i] = ((const float4*)(h2 + (size_t)b * Hd))[i];
    __syncthreads();
    const float4* w = (const float4*)(Wout + (size_t)o * Hd);
    float acc = 0.f;
#pragma unroll 8
    for (int i = 0; i < Hd / 4; ++i) {
        float4 wv = w[i], hv = ((float4*)hs)[i];
        acc += wv.x * hv.x + wv.y * hv.y + wv.z * hv.z + wv.w * hv.w;
    }
    acc += bout[o];
    __nv_bfloat16 hh = __float2bfloat16(acc);
    __nv_bfloat16 hl = __float2bfloat16(acc - __bfloat162float(hh));
    __nv_bfloat16* p = P0next + (size_t)b * K30P;
    p[o] = hh; p[1088 + o] = hh; p[2176 + o] = hl;
    dout[(size_t)b * Sq * Od + (size_t)t * Od + o] = acc;
}

// ---------------- host ----------------
extern "C" void kernel_launch(void* const* d_in, const int* in_sizes, int n_in,
                              void* d_out, int out_size)
{
    const float* z    = (const float*)d_in[0];
    const float* Wh   = (const float*)d_in[1];
    const float* bh   = (const float*)d_in[2];
    const float* Wc   = (const float*)d_in[3];
    const float* bc   = (const float*)d_in[4];
    const float* Wih0 = (const float*)d_in[5];
    const float* Whh0 = (const float*)d_in[6];
    const float* bih0 = (const float*)d_in[7];
    const float* bhh0 = (const float*)d_in[8];
    const float* Wih1 = (const float*)d_in[9];
    const float* Whh1 = (const float*)d_in[10];
    const float* bih1 = (const float*)d_in[11];
    const float* bhh1 = (const float*)d_in[12];
    const float* Wout = (const float*)d_in[13];
    const float* bout = (const float*)d_in[14];
    float* out = (float*)d_out;

    __nv_bfloat16 *p_W0, *p_W1, *p_P0, *p_P1;
    float *p_Gzp, *p_b1p, *p_cT1, *p_cT2, *p_h2f;
    cudaGetSymbolAddress((void**)&p_W0,  g_W0);
    cudaGetSymbolAddress((void**)&p_W1,  g_W1);
    cudaGetSymbolAddress((void**)&p_P0,  g_P0);
    cudaGetSymbolAddress((void**)&p_P1,  g_P1);
    cudaGetSymbolAddress((void**)&p_Gzp, g_Gzp);
    cudaGetSymbolAddress((void**)&p_b1p, g_b1p);
    cudaGetSymbolAddress((void**)&p_cT1, g_cT1);
    cudaGetSymbolAddress((void**)&p_cT2, g_cT2);
    cudaGetSymbolAddress((void**)&p_h2f, g_h2f);

    cudaFuncSetAttribute(lstm_mma, cudaFuncAttributeMaxDynamicSharedMemorySize, SMEM_TOTAL);

    pack_weights<<<G4, 256>>>(Wih0, Whh0, bih0, bhh0, Wih1, Whh1, bih1, bhh1);
    init_hc<<<dim3(Hd / 128, Bsz / 8), 128>>>(z, Wh, bh, Wc, bc);
    gz_gemm<<<dim3(G4 / 128, Bsz / 8), 128>>>(z);

    dim3 gg(G4 / 64, Bsz / 128);     // 64 x 4 = 256 CTAs
    const size_t P0sz = (size_t)Bsz * K30P, P1sz = (size_t)Bsz * K31;
    for (int t = 0; t < Sq; ++t) {
        int cur = t & 1, nxt = cur ^ 1;
        __nv_bfloat16* P0c = p_P0 + cur * P0sz;
        __nv_bfloat16* P0n = p_P0 + nxt * P0sz;
        __nv_bfloat16* P1c = p_P1 + cur * P1sz;
        __nv_bfloat16* P1n = p_P1 + nxt * P1sz;

        // layer 0: gates = Gzp + [fbh h1h | fbh h1h | fbl h1l | 0] @ W0cat.T
        EpiDst e0{P1c + 0,  P1c + 2048, P1c + 4096, K31};   // h1n -> layer1 panel (this step)
        EpiDst e1{P0n + 64, P0n + 1152, P0n + 2240, K30P};  // h1n -> layer0 panel (next step)
        lstm_mma<<<gg, 256, SMEM_TOTAL>>>(P0c, K30P, K30P / BK, p_W0,
                                          p_Gzp, nullptr, p_cT1, e0, e1, nullptr);

        // layer 1: gates = b1p + [h1nh h2h | h1nh h2h | h1nl h2l] @ W1cat.T
        EpiDst f0{P1n + 1024, P1n + 3072, P1n + 5120, K31}; // h2 -> layer1 panel (next step)
        EpiDst f1{nullptr, nullptr, nullptr, 0};
        lstm_mma<<<gg, 256, SMEM_TOTAL>>>(P1c, K31, K31 / BK, p_W1,
                                          nullptr, p_b1p, p_cT2, f0, f1, p_h2f);

        out_proj<<<Bsz, 64>>>(p_h2f, Wout, bout, out, t, P0n);
    }
}